// round 13
// baseline (speedup 1.0000x reference)
#include <cuda_runtime.h>
#include <cstdint>

#define BB 128
#define SS 32768
#define PP 65536
#define POS_W 5.0f
#define GRID 512
#define NT 256
#define NTHREADS (GRID * NT)            // 131072
#define SCAT_ITERS ((BB * PP / 4) / NTHREADS)   // 16
#define LOSS_ITERS ((BB * SS / 8) / NTHREADS)   // 4

// Scratch (allocation-free rule: __device__ globals).
// g_bit: 512 KB gt bitmap — L2-resident. Zero at module load; phase 2
// re-zeroes each word after reading it, restoring the invariant per replay.
__device__ unsigned g_bit[(size_t)BB * SS / 32];
__device__ double g_acc;      // zero at load; last block resets each call
__device__ unsigned g_done;   // ditto
__device__ unsigned g_bar;    // monotone epoch barrier counter (never reset)

// ---------------------------------------------------------------------------
// ONE kernel, two phases separated by a software grid barrier.
// Co-residency guarantee: __launch_bounds__(256,4) caps regs at 64 ->
// 4 blocks/SM resident; GRID=512 <= 4 * 128 SMs (sm_100a has 148) -> every
// block is running before any block can block on the barrier.
//
// Phase 1 (scatter): 4 entries/thread/iter, 16 grid-stride iters over the
// 8.4M path entries. Per-warp dtype probe (odd 32-bit words at mid-batch
// positions: zero under int64 layout, pj median under int32 -> nonzero).
// pj sorted per batch => is_first == (pj[k] != pj[k-1]); 3 of 4 prevs are
// in-register, entry 0's comes from the neighbor lane (shuffle), lane 0
// loads the one straggler scalar (L2-hot). Hits OR one bit into the
// L2-resident bitmap (spread-address REDG-class atomics).
//
// Barrier: epoch counter. token=atomicAdd(g_bar); target=(token/GRID+1)*GRID;
// spin until g_bar >= target. Monotone across graph replays (no reset);
// launches are stream-serialized so epochs never interleave.
//
// Phase 2 (loss): 8 elems/thread/iter, 4 iters. 4 threads share one bitmap
// word; after reading, the designated thread re-zeroes it (syncwarp-ordered).
// loss = 5*gt*softplus(-x) + (1-gt)*softplus(x);
// softplus(x) = max(x,0) + log(1+exp(-|x|)), MUFU fast-math (log arg in
// [1,2] -> abs err ~1e-7). Block sums -> one double atomicAdd; the last
// block writes the mean and resets the accumulators.
// ---------------------------------------------------------------------------
__global__ void __launch_bounds__(NT, 4)
fused_kernel(const void* __restrict__ paths_v,
             const int* __restrict__ targets,
             const float* __restrict__ preds,
             float* __restrict__ out) {
    const unsigned tid  = threadIdx.x;
    const unsigned lane = tid & 31;
    const unsigned gtid = blockIdx.x * NT + tid;

    // --- dtype probe (warp-uniform) ---
    unsigned det = 0;
    if (lane < 8) {
        size_t entry = ((size_t)lane << 20) + 32768;     // mid-batch positions
        det = ((const unsigned*)paths_v)[entry * 2 + 1]; // odd word
    }
    const bool is32 = __any_sync(0xFFFFFFFFu, det != 0u);

    // ---------------- Phase 1: scatter ----------------
#pragma unroll 2
    for (int it = 0; it < SCAT_ITERS; ++it) {
        unsigned t = it * NTHREADS + gtid;   // quad-entry index, < 2^21
        unsigned k0 = (t & 16383) * 4;       // first entry's step within batch
        unsigned b  = t >> 14;               // P/4 = 2^14 quads per batch

        int pi[4], pj[4];
        if (is32) {
            const int4* p = (const int4*)paths_v + (size_t)2 * t;
            int4 v0 = __ldcs(p);
            int4 v1 = __ldcs(p + 1);
            pi[0] = v0.x; pj[0] = v0.y; pi[1] = v0.z; pj[1] = v0.w;
            pi[2] = v1.x; pj[2] = v1.y; pi[3] = v1.z; pj[3] = v1.w;
        } else {
            const uint4* p = (const uint4*)paths_v + (size_t)4 * t;
            uint4 v0 = __ldcs(p);
            uint4 v1 = __ldcs(p + 1);
            uint4 v2 = __ldcs(p + 2);
            uint4 v3 = __ldcs(p + 3);
            pi[0] = (int)v0.x; pj[0] = (int)v0.z;        // low words (LE)
            pi[1] = (int)v1.x; pj[1] = (int)v1.z;
            pi[2] = (int)v2.x; pj[2] = (int)v2.z;
            pi[3] = (int)v3.x; pj[3] = (int)v3.z;
        }

        int prev = __shfl_up_sync(0xFFFFFFFFu, pj[3], 1);
        if (lane == 0) {
            if (k0 == 0) prev = -1;
            else prev = is32
                ? ((const int*)paths_v)[((size_t)b * PP + k0 - 1) * 2 + 1]
                : (int)((const unsigned*)paths_v)
                      [((size_t)b * PP + k0 - 1) * 4 + 2];
        }

        const int* trow = targets + (size_t)b * SS;
        unsigned* brow = g_bit + (size_t)b * (SS / 32);
#pragma unroll
        for (int j = 0; j < 4; ++j) {
            if (pj[j] != prev && trow[pj[j]] == 1)
                atomicOr(&brow[pi[j] >> 5], 1u << (pi[j] & 31));
            prev = pj[j];
        }
    }

    // ---------------- Grid barrier (epoch, monotone) ----------------
    __syncthreads();
    __shared__ unsigned bar_tgt;
    if (tid == 0) {
        __threadfence();                                  // release our ORs
        unsigned token = atomicAdd(&g_bar, 1u);
        bar_tgt = (token / GRID + 1u) * GRID;
    }
    __syncthreads();
    if (tid == 0) {
        while (*((volatile unsigned*)&g_bar) < bar_tgt)
            __nanosleep(64);
        __threadfence();                                  // acquire all ORs
    }
    __syncthreads();

    // ---------------- Phase 2: loss ----------------
    float sum = 0.0f;
#pragma unroll
    for (int it = 0; it < LOSS_ITERS; ++it) {
        unsigned i = it * NTHREADS + gtid;    // octo-element index, < 2^19
        float4 p0 = ((const float4*)preds)[(size_t)2 * i];
        float4 p1 = ((const float4*)preds)[(size_t)2 * i + 1];

        unsigned wrd = i >> 2;                // 4 threads per bitmap word
        unsigned gw = g_bit[wrd];
        __syncwarp();
        if ((i & 3) == 0) g_bit[wrd] = 0u;    // re-zero for next replay
        unsigned sh = (i & 3u) * 8u;          // our 8 bits

        float xv[8] = {p0.x, p0.y, p0.z, p0.w, p1.x, p1.y, p1.z, p1.w};
#pragma unroll
        for (int j = 0; j < 8; ++j) {
            float x = xv[j];
            float tl = __logf(1.0f + __expf(-fabsf(x)));
            bool gt = (gw >> (sh + j)) & 1u;
            sum += gt ? POS_W * (fmaxf(-x, 0.0f) + tl)
                      : (fmaxf(x, 0.0f) + tl);
        }
    }

    // block reduce
#pragma unroll
    for (int off = 16; off > 0; off >>= 1)
        sum += __shfl_xor_sync(0xFFFFFFFFu, sum, off);
    __shared__ float ws[NT / 32];
    if (lane == 0) ws[tid >> 5] = sum;
    __syncthreads();
    if (tid == 0) {
        float v = 0.0f;
#pragma unroll
        for (int j = 0; j < NT / 32; ++j) v += ws[j];
        atomicAdd(&g_acc, (double)v);
        __threadfence();
        unsigned done = atomicAdd(&g_done, 1u);
        if (done == GRID - 1) {
            // Every other block's g_acc add is fenced before its g_done
            // increment; observing the final count makes the sum visible.
            double s = *((volatile double*)&g_acc);
            out[0] = (float)(s * (1.0 / ((double)BB * (double)SS)));
            g_acc = 0.0;          // reset for next graph replay
            g_done = 0u;
        }
    }
}

extern "C" void kernel_launch(void* const* d_in, const int* in_sizes, int n_in,
                              void* d_out, int out_size) {
    // paths is uniquely the largest input (B*P*2 elements). Among the rest,
    // preds precedes targets in both dict and alphabetical orderings.
    int pi_idx = 0;
    for (int i = 1; i < n_in; ++i)
        if (in_sizes[i] > in_sizes[pi_idx]) pi_idx = i;

    const void* paths = d_in[pi_idx];
    const float* preds = nullptr;
    const int*   targets = nullptr;
    for (int i = 0; i < n_in; ++i) {
        if (i == pi_idx) continue;
        if (!preds) preds = (const float*)d_in[i];
        else        targets = (const int*)d_in[i];
    }
    float* out = (float*)d_out;

    fused_kernel<<<GRID, NT>>>(paths, targets, preds, out);
}

// round 14
// speedup vs baseline: 1.4769x; 1.4769x over previous
#include <cuda_runtime.h>
#include <cstdint>

#define BB 128
#define SS 32768
#define PP 65536
#define POS_W 5.0f

// Scratch (allocation-free rule: __device__ globals).
// g_bit: 512 KB gt bitmap — L2-resident. Zero at module load; loss_kernel
// re-zeroes each word after reading it, restoring the invariant per replay.
__device__ unsigned g_bit[(size_t)BB * SS / 32];
__device__ double g_acc;      // zero at load; last loss block resets each call
__device__ unsigned g_done;   // ditto

// ---------------------------------------------------------------------------
// Kernel 1: scatter (unchanged from the 30.9us best). FOUR entries per thread
// (B*P/4 = 2,097,152 threads), full-chip grid, no phases -> max MLP against
// the 64 MB paths stream.
//
// Per-warp dtype probe: 8 odd 32-bit words at mid-batch entry positions
// (max word 14,745,665 < 16,777,216 -> in-bounds under int32 and int64).
// int64 layout -> odd words are hi-halves of values < 2^15 -> all zero.
// int32 layout -> words are mid-batch pj values (nonzero a.s.).
//
// pj sorted per batch => is_first == (pj[k] != pj[k-1]). prev for entries
// 1..3 is in-register; entry 0's prev comes from the neighbor lane's pj[3]
// (shuffle); lane 0 loads the one straggler scalar (L2-hot).
// hit => atomicOr of one bit into the L2-resident bitmap (REDG, spread).
// ---------------------------------------------------------------------------
__global__ void scatter_kernel(const void* __restrict__ paths_v,
                               const int* __restrict__ targets) {
    const unsigned lane = threadIdx.x & 31;

    // --- dtype probe (warp-uniform) ---
    unsigned det = 0;
    if (lane < 8) {
        size_t entry = ((size_t)lane << 20) + 32768;     // mid-batch positions
        det = ((const unsigned*)paths_v)[entry * 2 + 1]; // odd word
    }
    const bool is32 = __any_sync(0xFFFFFFFFu, det != 0u);

    unsigned t = blockIdx.x * blockDim.x + threadIdx.x;  // < B*P/4 = 2^21
    unsigned k0 = (t & 16383) * 4;     // first entry's step within batch
    unsigned b  = t >> 14;             // P/4 = 2^14 threads per batch

    int pi[4], pj[4];
    if (is32) {
        const int4* p = (const int4*)paths_v + (size_t)2 * t;  // 2 entries/int4
        int4 v0 = __ldcs(p);
        int4 v1 = __ldcs(p + 1);
        pi[0] = v0.x; pj[0] = v0.y; pi[1] = v0.z; pj[1] = v0.w;
        pi[2] = v1.x; pj[2] = v1.y; pi[3] = v1.z; pj[3] = v1.w;
    } else {
        const uint4* p = (const uint4*)paths_v + (size_t)4 * t; // 1 entry/uint4
        uint4 v0 = __ldcs(p);
        uint4 v1 = __ldcs(p + 1);
        uint4 v2 = __ldcs(p + 2);
        uint4 v3 = __ldcs(p + 3);
        pi[0] = (int)v0.x; pj[0] = (int)v0.z;            // low words (LE)
        pi[1] = (int)v1.x; pj[1] = (int)v1.z;
        pi[2] = (int)v2.x; pj[2] = (int)v2.z;
        pi[3] = (int)v3.x; pj[3] = (int)v3.z;
    }

    int prev = __shfl_up_sync(0xFFFFFFFFu, pj[3], 1);
    if (lane == 0) {
        if (k0 == 0) prev = -1;
        else prev = is32
            ? ((const int*)paths_v)[((size_t)b * PP + k0 - 1) * 2 + 1]
            : (int)((const unsigned*)paths_v)[((size_t)b * PP + k0 - 1) * 4 + 2];
    }

    const int* trow = targets + (size_t)b * SS;
    unsigned* brow = g_bit + (size_t)b * (SS / 32);
#pragma unroll
    for (int j = 0; j < 4; ++j) {
        if (pj[j] != prev && trow[pj[j]] == 1)
            atomicOr(&brow[pi[j] >> 5], 1u << (pi[j] & 31));
        prev = pj[j];
    }
}

// ---------------------------------------------------------------------------
// Kernel 2: loss + reduction + finalize + bitmap re-zero. SIXTEEN elements
// per thread (4x float4 preds + half a bitmap word). All 5 loads are issued
// back-to-back before any consumer -> MLP 5 per thread (the R12 version was
// latency-bound at issue=23%). 2 threads share one bitmap word; after both
// lanes read, the even thread stores 0 (syncwarp-ordered), restoring the
// cleared invariant for the next replay.
// loss = 5*gt*softplus(-x)+(1-gt)*softplus(x);
// softplus(x) = max(x,0) + log(1+exp(-|x|)), MUFU fast-math (log arg in
// [1,2] -> abs err ~1e-7, negligible vs the 1e-3 threshold).
// Last finished block writes the mean and resets the accumulators.
// ---------------------------------------------------------------------------
__global__ void loss_kernel(const float* __restrict__ preds,
                            float* __restrict__ out) {
    unsigned i = blockIdx.x * blockDim.x + threadIdx.x;   // < B*S/16 = 2^18
    const float4* p = (const float4*)preds + (size_t)4 * i;
    float4 p0 = p[0];
    float4 p1 = p[1];
    float4 p2 = p[2];
    float4 p3 = p[3];
    unsigned wrd = i >> 1;                // 2 threads per bitmap word
    unsigned gw = g_bit[wrd];
    __syncwarp();
    if ((i & 1) == 0) g_bit[wrd] = 0u;    // re-zero for next replay
    unsigned sh = (i & 1u) * 16u;         // our 16 bits

    float xv[16] = {p0.x, p0.y, p0.z, p0.w, p1.x, p1.y, p1.z, p1.w,
                    p2.x, p2.y, p2.z, p2.w, p3.x, p3.y, p3.z, p3.w};
    float sum = 0.0f;
#pragma unroll
    for (int j = 0; j < 16; ++j) {
        float x = xv[j];
        float t = __logf(1.0f + __expf(-fabsf(x)));
        bool gt = (gw >> (sh + j)) & 1u;
        sum += gt ? POS_W * (fmaxf(-x, 0.0f) + t)
                  : (fmaxf(x, 0.0f) + t);
    }

    // warp reduce
#pragma unroll
    for (int off = 16; off > 0; off >>= 1)
        sum += __shfl_xor_sync(0xFFFFFFFFu, sum, off);

    __shared__ float ws[8];
    int w = threadIdx.x >> 5;
    if ((threadIdx.x & 31) == 0) ws[w] = sum;
    __syncthreads();
    if (threadIdx.x == 0) {
        float v = 0.0f;
#pragma unroll
        for (int j = 0; j < 8; ++j) v += ws[j];
        atomicAdd(&g_acc, (double)v);
        __threadfence();
        unsigned done = atomicAdd(&g_done, 1u);
        if (done == gridDim.x - 1) {
            // Every other block's g_acc add is fenced before its g_done
            // increment; observing the final count makes the sum visible.
            double s = *((volatile double*)&g_acc);
            out[0] = (float)(s * (1.0 / ((double)BB * (double)SS)));
            g_acc = 0.0;          // reset for next graph replay
            g_done = 0u;
        }
    }
}

extern "C" void kernel_launch(void* const* d_in, const int* in_sizes, int n_in,
                              void* d_out, int out_size) {
    // paths is uniquely the largest input (B*P*2 elements). Among the rest,
    // preds precedes targets in both dict and alphabetical orderings.
    int pi_idx = 0;
    for (int i = 1; i < n_in; ++i)
        if (in_sizes[i] > in_sizes[pi_idx]) pi_idx = i;

    const void* paths = d_in[pi_idx];
    const float* preds = nullptr;
    const int*   targets = nullptr;
    for (int i = 0; i < n_in; ++i) {
        if (i == pi_idx) continue;
        if (!preds) preds = (const float*)d_in[i];
        else        targets = (const int*)d_in[i];
    }
    float* out = (float*)d_out;

    scatter_kernel<<<(BB * PP / 4) / 256, 256>>>(paths, targets); // 4 entr/thr
    loss_kernel<<<(BB * SS / 16) / 256, 256>>>(preds, out);       // 16 elem/thr
}